// round 6
// baseline (speedup 1.0000x reference)
#include <cuda_runtime.h>
#include <cuda_bf16.h>
#include <cstdint>

// Problem constants: PROJ=128, H=128, G=2, D=96, T=33, NEG=-1e9

#define NEG_VAL (-1000000000.0f)

// Scratch (device globals -- no allocations allowed)
__device__ float g_E[2 * 33 * 96 * 128];   // node embeddings
__device__ float g_A[2 * 32 * 96 * 128];   // xne @ udW1[0:128]
__device__ float g_B[2 * 32 * 96 * 128];   // xce @ udW1[128:256]
__device__ float g_C[2 * 96 * 96 * 128];   // ee  @ udW1[256:288]

// ---- tf32 helpers -----------------------------------------------------------
__device__ __forceinline__ uint32_t tf32r(float x) {
    uint32_t r;
    asm("cvt.rna.tf32.f32 %0, %1;" : "=r"(r) : "f"(x));
    return r;
}
__device__ __forceinline__ void mma_tf32(float c[4], uint32_t a0, uint32_t a1,
                                         uint32_t a2, uint32_t a3,
                                         uint32_t b0, uint32_t b1) {
    asm("mma.sync.aligned.m16n8k8.row.col.f32.tf32.tf32.f32 "
        "{%0,%1,%2,%3},{%4,%5,%6,%7},{%8,%9},{%0,%1,%2,%3};"
        : "+f"(c[0]), "+f"(c[1]), "+f"(c[2]), "+f"(c[3])
        : "r"(a0), "r"(a1), "r"(a2), "r"(a3), "r"(b0), "r"(b1));
}

// ---------------------------------------------------------------------------
// Kernel 1: node embeddings  E = relu(relu(x @ neW1 + b1) @ neW2 + b2)
// 16 rows (same g,t; consecutive i) per block, 128 threads.
// ---------------------------------------------------------------------------
#define EROWS 16
__global__ void k_node_embed(const float* __restrict__ x,
                             const float* __restrict__ W1, const float* __restrict__ b1,
                             const float* __restrict__ W2, const float* __restrict__ b2) {
    int r0 = blockIdx.x * EROWS;
    int tid = threadIdx.x;  // 128
    __shared__ float xv[EROWS][129];
    __shared__ float y1[EROWS][128];

    int g = r0 / (33 * 96);
    int rem = r0 % (33 * 96);
    int t = rem / 96;
    int i0 = rem % 96;                 // multiple of 16 -> all rows same (g,t)
    const float* xb = x + (size_t)(g * 33 + t) * 128 * 192 + 96 * g + i0;

#pragma unroll
    for (int it = 0; it < 16; it++) {
        int e = tid + it * 128;        // e in [0,2048)
        int h = e >> 4;                // 0..127
        int ii = e & 15;               // 0..15
        xv[ii][h] = xb[h * 192 + ii];
    }
    __syncthreads();

    float acc[EROWS];
#pragma unroll
    for (int r = 0; r < EROWS; r++) acc[r] = b1[tid];
    for (int k = 0; k < 128; k++) {
        float w = W1[k * 128 + tid];
#pragma unroll
        for (int r = 0; r < EROWS; r++) acc[r] += xv[r][k] * w;
    }
#pragma unroll
    for (int r = 0; r < EROWS; r++) y1[r][tid] = fmaxf(acc[r], 0.0f);
    __syncthreads();

#pragma unroll
    for (int r = 0; r < EROWS; r++) acc[r] = b2[tid];
    for (int k = 0; k < 128; k++) {
        float w = W2[k * 128 + tid];
#pragma unroll
        for (int r = 0; r < EROWS; r++) acc[r] += y1[r][k] * w;
    }
#pragma unroll
    for (int r = 0; r < EROWS; r++) g_E[(r0 + r) * 128 + tid] = fmaxf(acc[r], 0.0f);
}

// ---------------------------------------------------------------------------
// Kernel 2: A/B projections + dist head.
// ---------------------------------------------------------------------------
#define PROWS 8
__global__ void k_proj_dist(const float* __restrict__ udW1,
                            const float* __restrict__ dpW1, const float* __restrict__ dpb1,
                            const float* __restrict__ dpW2, const float* __restrict__ dpb2,
                            const float* __restrict__ dpW3, const float* __restrict__ dpb3,
                            float* __restrict__ dist_out) {
    int r0 = blockIdx.x * PROWS;
    int tid = threadIdx.x;  // 128
    int g = r0 / (32 * 96);
    int rem = r0 % (32 * 96);
    int t = rem / 96;
    int i0 = rem % 96;

    __shared__ float Ec[PROWS][128];
    __shared__ float En[PROWS][128];
    __shared__ float y1d[PROWS][128];

    for (int e = tid; e < PROWS * 128; e += 128) {
        int r = e >> 7, k = e & 127;
        Ec[r][k] = g_E[((g * 33 + t) * 96 + i0 + r) * 128 + k];
        En[r][k] = g_E[((g * 33 + t + 1) * 96 + i0 + r) * 128 + k];
    }
    __syncthreads();

    float accA[PROWS], accB[PROWS], accD[PROWS];
#pragma unroll
    for (int r = 0; r < PROWS; r++) { accA[r] = 0.0f; accB[r] = 0.0f; accD[r] = 0.0f; }

    for (int k = 0; k < 128; k++) {
        float wa = udW1[k * 128 + tid];
        float wb = udW1[(128 + k) * 128 + tid];
        float wc = dpW1[k * 128 + tid];
        float wd = dpW1[(128 + k) * 128 + tid];
#pragma unroll
        for (int r = 0; r < PROWS; r++) {
            accA[r] += En[r][k] * wa;
            accB[r] += Ec[r][k] * wb;
            accD[r] += Ec[r][k] * wc + En[r][k] * wd;
        }
    }
    float db1 = dpb1[tid];
#pragma unroll
    for (int r = 0; r < PROWS; r++) {
        g_A[(r0 + r) * 128 + tid] = accA[r];
        g_B[(r0 + r) * 128 + tid] = accB[r];
        y1d[r][tid] = fmaxf(accD[r] + db1, 0.0f);
    }
    __syncthreads();

    int r = tid >> 4;
    int q = tid & 15;
    float s = 0.0f;
#pragma unroll
    for (int nn = 0; nn < 4; nn++) {
        int n = q * 4 + nn;
        float a = dpb2[n];
        for (int k = 0; k < 128; k++) a += y1d[r][k] * dpW2[k * 64 + n];
        s += fmaxf(a, 0.0f) * dpW3[n];
    }
#pragma unroll
    for (int off = 8; off; off >>= 1) s += __shfl_xor_sync(0xffffffffu, s, off);
    if (q == 0) dist_out[r0 + r] = s + dpb3[0];
}

// ---------------------------------------------------------------------------
// Kernel 3: edge MLP + C projection.
// ---------------------------------------------------------------------------
__global__ void k_ee_c(const float* __restrict__ edge_w,
                       const float* __restrict__ eeW1, const float* __restrict__ eeb1,
                       const float* __restrict__ eeW2, const float* __restrict__ eeb2,
                       const float* __restrict__ udW1) {
    int g = blockIdx.x / 96;
    int i = blockIdx.x % 96;
    int tid = threadIdx.x;  // 128

    __shared__ float l2s[96][33];
    __shared__ float w1s[32], b1s[32], b2s[32];
    __shared__ float w2s[32 * 32];
    __shared__ float w1cs[32 * 128];
    __shared__ float ews[96];

    if (tid < 32) { w1s[tid] = eeW1[tid]; b1s[tid] = eeb1[tid]; b2s[tid] = eeb2[tid]; }
    for (int e = tid; e < 1024; e += 128) w2s[e] = eeW2[e];
    for (int e = tid; e < 4096; e += 128) w1cs[e] = udW1[256 * 128 + e];
    if (tid < 96) ews[tid] = edge_w[(96 * g + i) * 192 + 96 * g + tid];
    __syncthreads();

    for (int e = tid; e < 96 * 32; e += 128) {
        int j = e >> 5, q = e & 31;
        float e0 = ews[j];
        float a = b2s[q];
#pragma unroll
        for (int p = 0; p < 32; p++) {
            float l1 = fmaxf(e0 * w1s[p] + b1s[p], 0.0f);
            a += l1 * w2s[p * 32 + q];
        }
        l2s[j][q] = fmaxf(a, 0.0f);
    }
    __syncthreads();

    float* Cout = g_C + (size_t)((g * 96 + i) * 96) * 128;
    for (int j = 0; j < 96; j++) {
        float a = 0.0f;
#pragma unroll
        for (int q = 0; q < 32; q++) a += l2s[j][q] * w1cs[q * 128 + tid];
        Cout[j * 128 + tid] = a;
    }
}

// ---------------------------------------------------------------------------
// Kernel 4 (dominant): tf32 mma.sync, t-batched.
// Block = (g, i, t-quartet): 192 threads = 6 warps; warp w owns m16 rows
// [16w,16w+16). Loops 4 t's reusing staged W2 (swizzled smem) and C base.
//   h[j,k] = relu(A[t,i,k]+B[t,j,k]+C[i,j,k]+b1[k]); y2 = relu(h@W2+b2);
//   logit = y2@W3+b3 (+mask)
// ---------------------------------------------------------------------------
#define TB 4
__global__ void __launch_bounds__(192) k_logits(const float* __restrict__ edge_w,
                                                const float* __restrict__ udb1,
                                                const float* __restrict__ udW2,
                                                const float* __restrict__ udb2,
                                                const float* __restrict__ udW3,
                                                const float* __restrict__ udb3,
                                                float* __restrict__ out) {
    int bid = blockIdx.x;                 // (g*96+i)*8 + tq
    int gi = bid >> 3;
    int tq = bid & 7;
    int g = gi / 96;
    int i = gi % 96;
    int t0 = tq * TB;
    int tid = threadIdx.x;
    int l = tid & 31;                     // lane
    int w = tid >> 5;                     // warp 0..5
    int tg = l & 3;                       // threadID_in_group
    int gp = l >> 2;                      // groupID 0..7
    int jb = w * 16;                      // warp's m16 row base

    __shared__ __align__(16) float sW2[128 * 64];   // 32 KB, xor-swizzled rows
    __shared__ __align__(16) float sh[96 * 36];     // h chunk [j][kc], stride 36
    __shared__ __align__(16) float sA[TB * 128];
    __shared__ float sW3[64];
    __shared__ float sb2[64];
    __shared__ float ews[96];

    // Stage W2 (tf32-rounded), per-row XOR-8 swizzle: phys n = n ^ (8*(k&3))
    for (int e = tid; e < 2048; e += 192) {
        int k = e >> 4, nq = e & 15;
        float4 v = reinterpret_cast<const float4*>(udW2)[e];
        v.x = __uint_as_float(tf32r(v.x));
        v.y = __uint_as_float(tf32r(v.y));
        v.z = __uint_as_float(tf32r(v.z));
        v.w = __uint_as_float(tf32r(v.w));
        int n0 = (nq * 4) ^ (8 * (k & 3));
        *reinterpret_cast<float4*>(sW2 + k * 64 + n0) = v;
    }
    for (int e = tid; e < TB * 128; e += 192) {
        int tt = e >> 7, k = e & 127;
        int arow = (g * 32 + t0 + tt) * 96 + i;
        sA[e] = g_A[(size_t)arow * 128 + k] + udb1[k];
    }
    if (tid < 64) { sW3[tid] = udW3[tid]; sb2[tid] = udb2[tid]; }
    if (tid >= 96 && tid < 192) {
        int j = tid - 96;
        ews[j] = edge_w[(size_t)(96 * g + i) * 192 + 96 * g + j];
    }

    const float* Cb = g_C + (size_t)((g * 96 + i) * 96) * 128;

    // Precompute swizzled W2 column per (lane, nt)
    int ncol[8];
#pragma unroll
    for (int nt = 0; nt < 8; nt++) ncol[nt] = (nt * 8 + gp) ^ (8 * tg);

    float b3 = udb3[0];

    for (int tt = 0; tt < TB; tt++) {
        int t = t0 + tt;
        const float* Bb = g_B + (size_t)((g * 32 + t) * 96) * 128;
        const float* sAt = sA + tt * 128;

        float acc[8][4];
#pragma unroll
        for (int nt = 0; nt < 8; nt++)
#pragma unroll
            for (int p = 0; p < 4; p++) acc[nt][p] = 0.0f;

        for (int kt = 0; kt < 4; kt++) {
            __syncthreads();  // guards sh reuse (and prologue smem first pass)
            // Build h chunk: 96 j x 32 k = 768 float4, 4 per thread
#pragma unroll
            for (int it = 0; it < 4; it++) {
                int e = tid + it * 192;
                int j = e >> 3, kq = e & 7;
                int k0 = kt * 32 + kq * 4;
                float4 b4 = *reinterpret_cast<const float4*>(Bb + j * 128 + k0);
                float4 c4 = *reinterpret_cast<const float4*>(Cb + j * 128 + k0);
                float4 a4 = *reinterpret_cast<const float4*>(sAt + k0);
                float4 v;
                v.x = __uint_as_float(tf32r(fmaxf(a4.x + b4.x + c4.x, 0.0f)));
                v.y = __uint_as_float(tf32r(fmaxf(a4.y + b4.y + c4.y, 0.0f)));
                v.z = __uint_as_float(tf32r(fmaxf(a4.z + b4.z + c4.z, 0.0f)));
                v.w = __uint_as_float(tf32r(fmaxf(a4.w + b4.w + c4.w, 0.0f)));
                *reinterpret_cast<float4*>(sh + j * 36 + kq * 4) = v;
            }
            __syncthreads();

#pragma unroll
            for (int k8 = 0; k8 < 4; k8++) {
                int kc = k8 * 8;
                uint32_t a0 = __float_as_uint(sh[(jb + gp) * 36 + kc + tg]);
                uint32_t a1 = __float_as_uint(sh[(jb + 8 + gp) * 36 + kc + tg]);
                uint32_t a2 = __float_as_uint(sh[(jb + gp) * 36 + kc + tg + 4]);
                uint32_t a3 = __float_as_uint(sh[(jb + 8 + gp) * 36 + kc + tg + 4]);
                const float* w2r0 = sW2 + (kt * 32 + kc + tg) * 64;
                const float* w2r1 = w2r0 + 4 * 64;
#pragma unroll
                for (int nt = 0; nt < 8; nt++) {
                    uint32_t b0 = __float_as_uint(w2r0[ncol[nt]]);
                    uint32_t b1 = __float_as_uint(w2r1[ncol[nt]]);
                    mma_tf32(acc[nt], a0, a1, a2, a3, b0, b1);
                }
            }
        }

        // Epilogue for this t
        float s0 = 0.0f, s1 = 0.0f;
#pragma unroll
        for (int nt = 0; nt < 8; nt++) {
            int n = nt * 8 + tg * 2;
            s0 += fmaxf(acc[nt][0] + sb2[n], 0.0f) * sW3[n]
                + fmaxf(acc[nt][1] + sb2[n + 1], 0.0f) * sW3[n + 1];
            s1 += fmaxf(acc[nt][2] + sb2[n], 0.0f) * sW3[n]
                + fmaxf(acc[nt][3] + sb2[n + 1], 0.0f) * sW3[n + 1];
        }
        s0 += __shfl_xor_sync(0xffffffffu, s0, 1);
        s0 += __shfl_xor_sync(0xffffffffu, s0, 2);
        s1 += __shfl_xor_sync(0xffffffffu, s1, 1);
        s1 += __shfl_xor_sync(0xffffffffu, s1, 2);
        if (tg == 0) {
            int j0 = jb + gp;
            float L0 = s0 + b3;
            float L1 = s1 + b3;
            if (ews[j0] == 0.0f && j0 != i) L0 = NEG_VAL;
            if (ews[j0 + 8] == 0.0f && (j0 + 8) != i) L1 = NEG_VAL;
            size_t orow = (size_t)((g * 32 + t) * 96 + i) * 96;
            out[orow + j0] = L0;
            out[orow + j0 + 8] = L1;
        }
    }
}

// ---------------------------------------------------------------------------
// Launch
// ---------------------------------------------------------------------------
extern "C" void kernel_launch(void* const* d_in, const int* in_sizes, int n_in,
                              void* d_out, int out_size) {
    int w0 = n_in - 20;
    const float* x      = (const float*)d_in[0];
    const float* edge_w = (const float*)d_in[1];
    const float* neW1 = (const float*)d_in[w0 + 0];
    const float* neb1 = (const float*)d_in[w0 + 1];
    const float* neW2 = (const float*)d_in[w0 + 2];
    const float* neb2 = (const float*)d_in[w0 + 3];
    const float* eeW1 = (const float*)d_in[w0 + 4];
    const float* eeb1 = (const float*)d_in[w0 + 5];
    const float* eeW2 = (const float*)d_in[w0 + 6];
    const float* eeb2 = (const float*)d_in[w0 + 7];
    const float* udW1 = (const float*)d_in[w0 + 8];
    const float* udb1 = (const float*)d_in[w0 + 9];
    const float* udW2 = (const float*)d_in[w0 + 10];
    const float* udb2 = (const float*)d_in[w0 + 11];
    const float* udW3 = (const float*)d_in[w0 + 12];
    const float* udb3 = (const float*)d_in[w0 + 13];
    const float* dpW1 = (const float*)d_in[w0 + 14];
    const float* dpb1 = (const float*)d_in[w0 + 15];
    const float* dpW2 = (const float*)d_in[w0 + 16];
    const float* dpb2 = (const float*)d_in[w0 + 17];
    const float* dpW3 = (const float*)d_in[w0 + 18];
    const float* dpb3 = (const float*)d_in[w0 + 19];

    float* out = (float*)d_out;
    const int CLASS_N = 2 * 32 * 96 * 96;  // 589824
    float* dist_out = out + CLASS_N;

    k_node_embed<<<6336 / EROWS, 128>>>(x, neW1, neb1, neW2, neb2);
    k_proj_dist<<<6144 / PROWS, 128>>>(udW1, dpW1, dpb1, dpW2, dpb2, dpW3, dpb3, dist_out);
    k_ee_c<<<2 * 96, 128>>>(edge_w, eeW1, eeb1, eeW2, eeb2, udW1);
    k_logits<<<2 * 96 * 8, 192>>>(edge_w, udb1, udW2, udb2, udW3, udb3, out);
}

// round 7
// speedup vs baseline: 1.0435x; 1.0435x over previous
#include <cuda_runtime.h>
#include <cuda_bf16.h>
#include <cstdint>

// Problem constants: PROJ=128, H=128, G=2, D=96, T=33, NEG=-1e9

#define NEG_VAL (-1000000000.0f)

// Scratch (device globals -- no allocations allowed)
__device__ float g_E[2 * 33 * 96 * 128];   // node embeddings
__device__ float g_A[2 * 32 * 96 * 128];   // xne @ udW1[0:128]
__device__ float g_B[2 * 32 * 96 * 128];   // xce @ udW1[128:256]
__device__ float g_C[2 * 96 * 96 * 128];   // ee  @ udW1[256:288]

// ---- tf32 helpers -----------------------------------------------------------
__device__ __forceinline__ uint32_t tf32r(float x) {
    uint32_t r;
    asm("cvt.rna.tf32.f32 %0, %1;" : "=r"(r) : "f"(x));
    return r;
}
__device__ __forceinline__ void mma_tf32(float c[4], uint32_t a0, uint32_t a1,
                                         uint32_t a2, uint32_t a3,
                                         uint32_t b0, uint32_t b1) {
    asm("mma.sync.aligned.m16n8k8.row.col.f32.tf32.tf32.f32 "
        "{%0,%1,%2,%3},{%4,%5,%6,%7},{%8,%9},{%0,%1,%2,%3};"
        : "+f"(c[0]), "+f"(c[1]), "+f"(c[2]), "+f"(c[3])
        : "r"(a0), "r"(a1), "r"(a2), "r"(a3), "r"(b0), "r"(b1));
}

// ---------------------------------------------------------------------------
// Kernel 1: node embeddings  E = relu(relu(x @ neW1 + b1) @ neW2 + b2)
// ---------------------------------------------------------------------------
#define EROWS 16
__global__ void k_node_embed(const float* __restrict__ x,
                             const float* __restrict__ W1, const float* __restrict__ b1,
                             const float* __restrict__ W2, const float* __restrict__ b2) {
    int r0 = blockIdx.x * EROWS;
    int tid = threadIdx.x;  // 128
    __shared__ float xv[EROWS][129];
    __shared__ float y1[EROWS][128];

    int g = r0 / (33 * 96);
    int rem = r0 % (33 * 96);
    int t = rem / 96;
    int i0 = rem % 96;
    const float* xb = x + (size_t)(g * 33 + t) * 128 * 192 + 96 * g + i0;

#pragma unroll
    for (int it = 0; it < 16; it++) {
        int e = tid + it * 128;
        int h = e >> 4;
        int ii = e & 15;
        xv[ii][h] = xb[h * 192 + ii];
    }
    __syncthreads();

    float acc[EROWS];
#pragma unroll
    for (int r = 0; r < EROWS; r++) acc[r] = b1[tid];
    for (int k = 0; k < 128; k++) {
        float w = W1[k * 128 + tid];
#pragma unroll
        for (int r = 0; r < EROWS; r++) acc[r] += xv[r][k] * w;
    }
#pragma unroll
    for (int r = 0; r < EROWS; r++) y1[r][tid] = fmaxf(acc[r], 0.0f);
    __syncthreads();

#pragma unroll
    for (int r = 0; r < EROWS; r++) acc[r] = b2[tid];
    for (int k = 0; k < 128; k++) {
        float w = W2[k * 128 + tid];
#pragma unroll
        for (int r = 0; r < EROWS; r++) acc[r] += y1[r][k] * w;
    }
#pragma unroll
    for (int r = 0; r < EROWS; r++) g_E[(r0 + r) * 128 + tid] = fmaxf(acc[r], 0.0f);
}

// ---------------------------------------------------------------------------
// Kernel 2: A/B projections + dist head.
// ---------------------------------------------------------------------------
#define PROWS 8
__global__ void k_proj_dist(const float* __restrict__ udW1,
                            const float* __restrict__ dpW1, const float* __restrict__ dpb1,
                            const float* __restrict__ dpW2, const float* __restrict__ dpb2,
                            const float* __restrict__ dpW3, const float* __restrict__ dpb3,
                            float* __restrict__ dist_out) {
    int r0 = blockIdx.x * PROWS;
    int tid = threadIdx.x;  // 128
    int g = r0 / (32 * 96);
    int rem = r0 % (32 * 96);
    int t = rem / 96;
    int i0 = rem % 96;

    __shared__ float Ec[PROWS][128];
    __shared__ float En[PROWS][128];
    __shared__ float y1d[PROWS][128];

    for (int e = tid; e < PROWS * 128; e += 128) {
        int r = e >> 7, k = e & 127;
        Ec[r][k] = g_E[((g * 33 + t) * 96 + i0 + r) * 128 + k];
        En[r][k] = g_E[((g * 33 + t + 1) * 96 + i0 + r) * 128 + k];
    }
    __syncthreads();

    float accA[PROWS], accB[PROWS], accD[PROWS];
#pragma unroll
    for (int r = 0; r < PROWS; r++) { accA[r] = 0.0f; accB[r] = 0.0f; accD[r] = 0.0f; }

    for (int k = 0; k < 128; k++) {
        float wa = udW1[k * 128 + tid];
        float wb = udW1[(128 + k) * 128 + tid];
        float wc = dpW1[k * 128 + tid];
        float wd = dpW1[(128 + k) * 128 + tid];
#pragma unroll
        for (int r = 0; r < PROWS; r++) {
            accA[r] += En[r][k] * wa;
            accB[r] += Ec[r][k] * wb;
            accD[r] += Ec[r][k] * wc + En[r][k] * wd;
        }
    }
    float db1 = dpb1[tid];
#pragma unroll
    for (int r = 0; r < PROWS; r++) {
        g_A[(r0 + r) * 128 + tid] = accA[r];
        g_B[(r0 + r) * 128 + tid] = accB[r];
        y1d[r][tid] = fmaxf(accD[r] + db1, 0.0f);
    }
    __syncthreads();

    int r = tid >> 4;
    int q = tid & 15;
    float s = 0.0f;
#pragma unroll
    for (int nn = 0; nn < 4; nn++) {
        int n = q * 4 + nn;
        float a = dpb2[n];
        for (int k = 0; k < 128; k++) a += y1d[r][k] * dpW2[k * 64 + n];
        s += fmaxf(a, 0.0f) * dpW3[n];
    }
#pragma unroll
    for (int off = 8; off; off >>= 1) s += __shfl_xor_sync(0xffffffffu, s, off);
    if (q == 0) dist_out[r0 + r] = s + dpb3[0];
}

// ---------------------------------------------------------------------------
// Kernel 3: edge MLP + C projection.
// ---------------------------------------------------------------------------
__global__ void k_ee_c(const float* __restrict__ edge_w,
                       const float* __restrict__ eeW1, const float* __restrict__ eeb1,
                       const float* __restrict__ eeW2, const float* __restrict__ eeb2,
                       const float* __restrict__ udW1) {
    int g = blockIdx.x / 96;
    int i = blockIdx.x % 96;
    int tid = threadIdx.x;  // 128

    __shared__ float l2s[96][33];
    __shared__ float w1s[32], b1s[32], b2s[32];
    __shared__ float w2s[32 * 32];
    __shared__ float w1cs[32 * 128];
    __shared__ float ews[96];

    if (tid < 32) { w1s[tid] = eeW1[tid]; b1s[tid] = eeb1[tid]; b2s[tid] = eeb2[tid]; }
    for (int e = tid; e < 1024; e += 128) w2s[e] = eeW2[e];
    for (int e = tid; e < 4096; e += 128) w1cs[e] = udW1[256 * 128 + e];
    if (tid < 96) ews[tid] = edge_w[(96 * g + i) * 192 + 96 * g + tid];
    __syncthreads();

    for (int e = tid; e < 96 * 32; e += 128) {
        int j = e >> 5, q = e & 31;
        float e0 = ews[j];
        float a = b2s[q];
#pragma unroll
        for (int p = 0; p < 32; p++) {
            float l1 = fmaxf(e0 * w1s[p] + b1s[p], 0.0f);
            a += l1 * w2s[p * 32 + q];
        }
        l2s[j][q] = fmaxf(a, 0.0f);
    }
    __syncthreads();

    float* Cout = g_C + (size_t)((g * 96 + i) * 96) * 128;
    for (int j = 0; j < 96; j++) {
        float a = 0.0f;
#pragma unroll
        for (int q = 0; q < 32; q++) a += l2s[j][q] * w1cs[q * 128 + tid];
        Cout[j * 128 + tid] = a;
    }
}

// ---------------------------------------------------------------------------
// Kernel 4 (dominant): per (g,t,i) logits via tf32 mma.sync.
// 192 threads = 6 warps; warp w owns ONE m16 tile (rows [16w,16w+16)),
// all 8 n8 tiles, K=128 as 16 k8 steps.
// W2 staged to smem with XOR-8 swizzle; h built per 32-k chunk (stride 36).
// __launch_bounds__(192,4): regs<=85 so 4 blocks/SM hold (24 warps/SM).
// ---------------------------------------------------------------------------
__global__ void __launch_bounds__(192, 4) k_logits(const float* __restrict__ edge_w,
                                                   const float* __restrict__ udb1,
                                                   const float* __restrict__ udW2,
                                                   const float* __restrict__ udb2,
                                                   const float* __restrict__ udW3,
                                                   const float* __restrict__ udb3,
                                                   float* __restrict__ out) {
    int bid = blockIdx.x;                 // g*32*96 + t*96 + i
    int g = bid / (32 * 96);
    int rem = bid % (32 * 96);
    int t = rem / 96;
    int i = rem % 96;
    int tid = threadIdx.x;
    int l = tid & 31;                     // lane
    int w = tid >> 5;                     // warp 0..5
    int tg = l & 3;                       // threadID_in_group
    int gp = l >> 2;                      // groupID 0..7
    int jb = w * 16;                      // warp's m16 row base

    __shared__ __align__(16) float sW2[128 * 64];   // 32 KB, xor-swizzled rows
    __shared__ __align__(16) float sh[96 * 36];     // h chunk [j][kc], stride 36
    __shared__ __align__(16) float sA[128];
    __shared__ float sW3[64];
    __shared__ float sb2[64];
    __shared__ float ews[96];

    // Stage W2 (tf32-rounded), per-row XOR-8 swizzle: phys n = n ^ (8*(k&3))
    for (int e = tid; e < 2048; e += 192) {
        int k = e >> 4, nq = e & 15;
        float4 v = reinterpret_cast<const float4*>(udW2)[e];
        v.x = __uint_as_float(tf32r(v.x));
        v.y = __uint_as_float(tf32r(v.y));
        v.z = __uint_as_float(tf32r(v.z));
        v.w = __uint_as_float(tf32r(v.w));
        int n0 = (nq * 4) ^ (8 * (k & 3));
        *reinterpret_cast<float4*>(sW2 + k * 64 + n0) = v;
    }
    if (tid < 128) sA[tid] = g_A[(size_t)bid * 128 + tid] + udb1[tid];
    if (tid >= 128) { int n = tid - 128; sW3[n] = udW3[n]; sb2[n] = udb2[n]; }
    if (tid < 96) ews[tid] = edge_w[(size_t)(96 * g + i) * 192 + 96 * g + tid];

    const float* Bb = g_B + (size_t)((g * 32 + t) * 96) * 128;
    const float* Cb = g_C + (size_t)((g * 96 + i) * 96) * 128;

    // Precompute swizzled W2 column per (lane, nt)
    int ncol[8];
#pragma unroll
    for (int nt = 0; nt < 8; nt++) ncol[nt] = (nt * 8 + gp) ^ (8 * tg);

    float acc[8][4];
#pragma unroll
    for (int nt = 0; nt < 8; nt++)
#pragma unroll
        for (int p = 0; p < 4; p++) acc[nt][p] = 0.0f;

    for (int kt = 0; kt < 4; kt++) {
        __syncthreads();  // guards sh reuse (and prologue smem on kt==0)
        // Build h chunk: 96 j x 32 k = 768 float4, 4 per thread
#pragma unroll
        for (int it = 0; it < 4; it++) {
            int e = tid + it * 192;
            int j = e >> 3, kq = e & 7;
            int k0 = kt * 32 + kq * 4;
            float4 b4 = *reinterpret_cast<const float4*>(Bb + j * 128 + k0);
            float4 c4 = *reinterpret_cast<const float4*>(Cb + j * 128 + k0);
            float4 a4 = *reinterpret_cast<const float4*>(sA + k0);
            float4 v;
            v.x = __uint_as_float(tf32r(fmaxf(a4.x + b4.x + c4.x, 0.0f)));
            v.y = __uint_as_float(tf32r(fmaxf(a4.y + b4.y + c4.y, 0.0f)));
            v.z = __uint_as_float(tf32r(fmaxf(a4.z + b4.z + c4.z, 0.0f)));
            v.w = __uint_as_float(tf32r(fmaxf(a4.w + b4.w + c4.w, 0.0f)));
            *reinterpret_cast<float4*>(sh + j * 36 + kq * 4) = v;
        }
        __syncthreads();

#pragma unroll
        for (int k8 = 0; k8 < 4; k8++) {
            int kc = k8 * 8;
            uint32_t a0 = __float_as_uint(sh[(jb + gp) * 36 + kc + tg]);
            uint32_t a1 = __float_as_uint(sh[(jb + 8 + gp) * 36 + kc + tg]);
            uint32_t a2 = __float_as_uint(sh[(jb + gp) * 36 + kc + tg + 4]);
            uint32_t a3 = __float_as_uint(sh[(jb + 8 + gp) * 36 + kc + tg + 4]);
            const float* w2r0 = sW2 + (kt * 32 + kc + tg) * 64;
            const float* w2r1 = w2r0 + 4 * 64;
#pragma unroll
            for (int nt = 0; nt < 8; nt++) {
                uint32_t b0 = __float_as_uint(w2r0[ncol[nt]]);
                uint32_t b1 = __float_as_uint(w2r1[ncol[nt]]);
                mma_tf32(acc[nt], a0, a1, a2, a3, b0, b1);
            }
        }
    }

    // Epilogue: relu + W3 dot + lane-group reduce + mask + store
    float b3 = udb3[0];
    float s0 = 0.0f, s1 = 0.0f;
#pragma unroll
    for (int nt = 0; nt < 8; nt++) {
        int n = nt * 8 + tg * 2;
        s0 += fmaxf(acc[nt][0] + sb2[n], 0.0f) * sW3[n]
            + fmaxf(acc[nt][1] + sb2[n + 1], 0.0f) * sW3[n + 1];
        s1 += fmaxf(acc[nt][2] + sb2[n], 0.0f) * sW3[n]
            + fmaxf(acc[nt][3] + sb2[n + 1], 0.0f) * sW3[n + 1];
    }
    s0 += __shfl_xor_sync(0xffffffffu, s0, 1);
    s0 += __shfl_xor_sync(0xffffffffu, s0, 2);
    s1 += __shfl_xor_sync(0xffffffffu, s1, 1);
    s1 += __shfl_xor_sync(0xffffffffu, s1, 2);
    if (tg == 0) {
        int j0 = jb + gp;
        float L0 = s0 + b3;
        float L1 = s1 + b3;
        if (ews[j0] == 0.0f && j0 != i) L0 = NEG_VAL;
        if (ews[j0 + 8] == 0.0f && (j0 + 8) != i) L1 = NEG_VAL;
        out[(size_t)bid * 96 + j0] = L0;
        out[(size_t)bid * 96 + j0 + 8] = L1;
    }
}

// ---------------------------------------------------------------------------
// Launch
// ---------------------------------------------------------------------------
extern "C" void kernel_launch(void* const* d_in, const int* in_sizes, int n_in,
                              void* d_out, int out_size) {
    int w0 = n_in - 20;
    const float* x      = (const float*)d_in[0];
    const float* edge_w = (const float*)d_in[1];
    const float* neW1 = (const float*)d_in[w0 + 0];
    const float* neb1 = (const float*)d_in[w0 + 1];
    const float* neW2 = (const float*)d_in[w0 + 2];
    const float* neb2 = (const float*)d_in[w0 + 3];
    const float* eeW1 = (const float*)d_in[w0 + 4];
    const float* eeb1 = (const float*)d_in[w0 + 5];
    const float* eeW2 = (const float*)d_in[w0 + 6];
    const float* eeb2 = (const float*)d_in[w0 + 7];
    const float* udW1 = (const float*)d_in[w0 + 8];
    const float* udb1 = (const float*)d_in[w0 + 9];
    const float* udW2 = (const float*)d_in[w0 + 10];
    const float* udb2 = (const float*)d_in[w0 + 11];
    const float* udW3 = (const float*)d_in[w0 + 12];
    const float* udb3 = (const float*)d_in[w0 + 13];
    const float* dpW1 = (const float*)d_in[w0 + 14];
    const float* dpb1 = (const float*)d_in[w0 + 15];
    const float* dpW2 = (const float*)d_in[w0 + 16];
    const float* dpb2 = (const float*)d_in[w0 + 17];
    const float* dpW3 = (const float*)d_in[w0 + 18];
    const float* dpb3 = (const float*)d_in[w0 + 19];

    float* out = (float*)d_out;
    const int CLASS_N = 2 * 32 * 96 * 96;  // 589824
    float* dist_out = out + CLASS_N;

    k_node_embed<<<6336 / EROWS, 128>>>(x, neW1, neb1, neW2, neb2);
    k_proj_dist<<<6144 / PROWS, 128>>>(udW1, dpW1, dpb1, dpW2, dpb2, dpW3, dpb3, dist_out);
    k_ee_c<<<2 * 96, 128>>>(edge_w, eeW1, eeb1, eeW2, eeb2, udW1);
    k_logits<<<2 * 32 * 96, 192>>>(edge_w, udb1, udW2, udb2, udW3, udb3, out);
}